// round 3
// baseline (speedup 1.0000x reference)
#include <cuda_runtime.h>
#include <math.h>

// ---------------------------------------------------------------------------
// Problem constants (fixed by setup_inputs): R=8192 rays, S=64 samples,
// C=32 feature channels, 6 planes coarse dims {64x64,64x64,64x50,64x64,64x50,64x50}
// Fine dims: H=128 for all; W in {128,128,100,128,100,100}.
// ---------------------------------------------------------------------------
#define NRAYS   8192
#define NSAMP   64
#define NPTS    (NRAYS * NSAMP)     // 524288
#define TPB     256
#define NTILES  (NPTS / TPB)        // 2048

// Channel-last fine plane sizes (floats): 128*128*32=524288, 128*100*32=409600
#define PL_TOTAL 2801664

__device__ float g_hi[PL_TOTAL];
__device__ float g_lo[PL_TOTAL];
__device__ float g_enc[NRAYS * 16];

// ---------------------------------------------------------------------------
// f32x2 packed-math helpers (sm_100+: FFMA2 only reachable via PTX fma.rn.f32x2)
// ---------------------------------------------------------------------------
__device__ __forceinline__ unsigned long long pack2(float a, float b) {
    unsigned long long r;
    asm("mov.b64 %0, {%1, %2};" : "=l"(r) : "f"(a), "f"(b));
    return r;
}
__device__ __forceinline__ void unpack2(unsigned long long v, float& a, float& b) {
    asm("mov.b64 {%0, %1}, %2;" : "=f"(a), "=f"(b) : "l"(v));
}
__device__ __forceinline__ void ffma2(unsigned long long& acc,
                                      unsigned long long a, unsigned long long b) {
    asm("fma.rn.f32x2 %0, %1, %2, %0;" : "+l"(acc) : "l"(a), "l"(b));
}

// ---------------------------------------------------------------------------
// Kernel 1: inverse Haar DWT, one plane per launch. Channel-last output.
// fine[2i][2j]=ee, fine[2i][2j+1]=eo, fine[2i+1][2j]=oe, fine[2i+1][2j+1]=oo
// lo plane = idwt(yl, 0): all four quadrants = 0.5*a.
// ---------------------------------------------------------------------------
__global__ void idwt_kernel(const float* __restrict__ yl,
                            const float* __restrict__ yh,
                            int outOff, int h, int w)
{
    int id = blockIdx.x * blockDim.x + threadIdx.x;
    int total = h * w * 32;
    if (id >= total) return;
    int c = id & 31;
    int rest = id >> 5;
    int j = rest % w;
    int i = rest / w;
    int hw = h * w;

    float a  = yl[c * hw + i * w + j];
    const float* yhb = yh + (size_t)c * 3 * hw + i * w + j;
    float lh = yhb[0];
    float hl = yhb[hw];
    float hh = yhb[2 * hw];

    int W2 = 2 * w;
    int o = outOff + ((2 * i) * W2 + 2 * j) * 32 + c;

    float ee = 0.5f * (a + lh + hl + hh);
    float eo = 0.5f * (a + lh - hl - hh);
    float oe = 0.5f * (a - lh + hl - hh);
    float oo = 0.5f * (a - lh - hl + hh);

    g_hi[o]                = ee;
    g_hi[o + 32]           = eo;
    g_hi[o + W2 * 32]      = oe;
    g_hi[o + W2 * 32 + 32] = oo;

    float l = 0.5f * a;
    g_lo[o]                = l;
    g_lo[o + 32]           = l;
    g_lo[o + W2 * 32]      = l;
    g_lo[o + W2 * 32 + 32] = l;
}

// ---------------------------------------------------------------------------
// Kernel 2: per-ray SH16 direction encoding
// ---------------------------------------------------------------------------
__global__ void enc_kernel(const float* __restrict__ dirs)
{
    int r = blockIdx.x * blockDim.x + threadIdx.x;
    if (r >= NRAYS) return;
    float x = dirs[3 * r + 0];
    float y = dirs[3 * r + 1];
    float z = dirs[3 * r + 2];
    float inv = 1.0f / sqrtf(x * x + y * y + z * z);
    x *= inv; y *= inv; z *= inv;
    float xx = x * x, yy = y * y, zz = z * z;

    float e[16];
    e[0]  = 0.28209479177387814f;
    e[1]  = -0.4886025119029199f * y;
    e[2]  = 0.4886025119029199f * z;
    e[3]  = -0.4886025119029199f * x;
    e[4]  = 1.0925484305920792f * x * y;
    e[5]  = -1.0925484305920792f * y * z;
    e[6]  = 0.31539156525252005f * (3.0f * zz - 1.0f);
    e[7]  = -1.0925484305920792f * x * z;
    e[8]  = 0.5462742152960396f * (xx - yy);
    e[9]  = -0.5900435899266435f * y * (3.0f * xx - yy);
    e[10] = 2.890611442640554f * x * y * z;
    e[11] = -0.4570457994644658f * y * (5.0f * zz - 1.0f);
    e[12] = 0.3731763325901154f * z * (5.0f * zz - 3.0f);
    e[13] = -0.4570457994644658f * x * (5.0f * zz - 1.0f);
    e[14] = 1.445305721320277f * z * (xx - yy);
    e[15] = -0.5900435899266435f * x * (xx - 3.0f * yy);

#pragma unroll
    for (int k = 0; k < 16; k++) g_enc[r * 16 + k] = e[k];
}

// ---------------------------------------------------------------------------
// Kernel 3: fused main kernel.
// Block = 256 threads, tile = 256 points.
// Phase 1: warp-per-point bilinear gathers (lane = channel, coalesced 128B).
// Phase 2: thread-per-point MLP chain, packed f32x2 math, smem weights.
// Shared memory (floats):
//   W1s   [0,4096)      Wsig1 64x64
//   W2s   [4096,5120)   Wsig2 64x16
//   Wc1s  [5120,7104)   Wc1   31x64
//   Wc2s  [7104,11200)  Wc2   64x64
//   Wc3s  [11200,11392) Wc3   64x3
//   fs    [11392,28032) 256 x 65 scratch rows (stride-65: conflict-free)
// Total 28032 floats = 112128 bytes.
// ---------------------------------------------------------------------------
#define SMEM_FLOATS 28032
#define SMEM_BYTES  (SMEM_FLOATS * 4)

__global__ void __launch_bounds__(TPB) wf_main(
    const float* __restrict__ pts,
    const float* __restrict__ ts,
    const float* __restrict__ W1,
    const float* __restrict__ W2,
    const float* __restrict__ Wc1,
    const float* __restrict__ Wc2,
    const float* __restrict__ Wc3,
    float* __restrict__ out)
{
    extern __shared__ float sm[];
    float* W1s  = sm;
    float* W2s  = sm + 4096;
    float* Wc1s = sm + 5120;
    float* Wc2s = sm + 7104;
    float* Wc3s = sm + 11200;
    float* fs   = sm + 11392;

    int tid = threadIdx.x;
    for (int i = tid; i < 4096; i += TPB) W1s[i]  = W1[i];
    for (int i = tid; i < 1024; i += TPB) W2s[i]  = W2[i];
    for (int i = tid; i < 1984; i += TPB) Wc1s[i] = Wc1[i];
    for (int i = tid; i < 4096; i += TPB) Wc2s[i] = Wc2[i];
    for (int i = tid; i < 192;  i += TPB) Wc3s[i] = Wc3[i];
    __syncthreads();

    const int lane = tid & 31;
    const int wrp  = tid >> 5;

    for (int tile = blockIdx.x; tile < NTILES; tile += gridDim.x) {
        int base = tile * TPB;

        // ---------------- Phase 1: interpolation ----------------
        {
            int myp = base + wrp * 32 + lane;
            float c0r = pts[3 * myp + 0];
            float c1r = pts[3 * myp + 1];
            float c2r = pts[3 * myp + 2];
            float c3r = ts[myp >> 6] * 2.0f - 1.0f;

            for (int it = 0; it < 32; it++) {
                float cc[4];
                cc[0] = __shfl_sync(0xffffffffu, c0r, it);
                cc[1] = __shfl_sync(0xffffffffu, c1r, it);
                cc[2] = __shfl_sync(0xffffffffu, c2r, it);
                cc[3] = __shfl_sync(0xffffffffu, c3r, it);

                float fh = 1.0f, fl = 1.0f;

                const int WplA[6] = {128, 128, 100, 128, 100, 100};
                const int OFFA[6] = {0, 524288, 1048576, 1458176, 1982464, 2392064};
                const int JA[6]   = {0, 0, 0, 1, 1, 2};
                const int KA[6]   = {1, 2, 3, 2, 3, 3};

#pragma unroll
                for (int pl = 0; pl < 6; pl++) {
                    const int Wp = WplA[pl];
                    float yv = (cc[JA[pl]] + 1.0f) * 0.5f * 127.0f;
                    float xv = (cc[KA[pl]] + 1.0f) * 0.5f * (float)(Wp - 1);
                    float y0f = fminf(fmaxf(floorf(yv), 0.0f), 127.0f);
                    float x0f = fminf(fmaxf(floorf(xv), 0.0f), (float)(Wp - 1));
                    float wy = fminf(fmaxf(yv - y0f, 0.0f), 1.0f);
                    float wx = fminf(fmaxf(xv - x0f, 0.0f), 1.0f);
                    int y0 = (int)y0f;
                    int x0 = (int)x0f;
                    int y1 = min(y0 + 1, 127);
                    int x1 = min(x0 + 1, Wp - 1);
                    float w00 = (1.0f - wy) * (1.0f - wx);
                    float w01 = (1.0f - wy) * wx;
                    float w10 = wy * (1.0f - wx);
                    float w11 = wy * wx;

                    int b00 = OFFA[pl] + (y0 * Wp + x0) * 32 + lane;
                    int b01 = OFFA[pl] + (y0 * Wp + x1) * 32 + lane;
                    int b10 = OFFA[pl] + (y1 * Wp + x0) * 32 + lane;
                    int b11 = OFFA[pl] + (y1 * Wp + x1) * 32 + lane;

                    float hv = w00 * g_hi[b00] + w01 * g_hi[b01]
                             + w10 * g_hi[b10] + w11 * g_hi[b11];
                    float lv = w00 * g_lo[b00] + w01 * g_lo[b01]
                             + w10 * g_lo[b10] + w11 * g_lo[b11];
                    fh *= hv;
                    fl *= lv;
                }

                int row = wrp * 32 + it;
                fs[row * 65 + lane]      = fh;
                fs[row * 65 + 32 + lane] = fl;
            }
        }
        __syncthreads();

        // ---------------- Phase 2: packed-f32x2 MLP chain ----------------
        {
            int p = base + tid;
            float* myrow = &fs[tid * 65];

            unsigned long long acc[32];

            // ---- Layer sig1 (64 -> 64): acc[q] = {out[2q], out[2q+1]} ----
#pragma unroll
            for (int q = 0; q < 32; q++) acc[q] = 0ull;
            for (int i = 0; i < 64; i++) {
                float s = myrow[i];
                unsigned long long ff = pack2(s, s);
                const ulonglong2* wr = reinterpret_cast<const ulonglong2*>(&W1s[i << 6]);
#pragma unroll
                for (int q = 0; q < 16; q++) {
                    ulonglong2 wv = wr[q];
                    ffma2(acc[2 * q],     ff, wv.x);
                    ffma2(acc[2 * q + 1], ff, wv.y);
                }
            }
            // relu -> store hidden h to own smem row
#pragma unroll
            for (int q = 0; q < 32; q++) {
                float a, b;
                unpack2(acc[q], a, b);
                myrow[2 * q]     = fmaxf(a, 0.0f);
                myrow[2 * q + 1] = fmaxf(b, 0.0f);
            }

            // ---- Layer sig2 (64 -> 16): o16p[k] = {o16[2k], o16[2k+1]} ----
            unsigned long long o16p[8];
#pragma unroll
            for (int k = 0; k < 8; k++) o16p[k] = 0ull;
            for (int j = 0; j < 64; j++) {
                float s = myrow[j];
                unsigned long long ff = pack2(s, s);
                const ulonglong2* wr = reinterpret_cast<const ulonglong2*>(&W2s[j << 4]);
#pragma unroll
                for (int q = 0; q < 4; q++) {
                    ulonglong2 wv = wr[q];
                    ffma2(o16p[2 * q],     ff, wv.x);
                    ffma2(o16p[2 * q + 1], ff, wv.y);
                }
            }

            // density = exp(clip(o16[15])); ci = [enc(16), geo(15)] into smem row
            float density;
            {
                int ray = p >> 6;
                const float* ep = &g_enc[ray * 16];
#pragma unroll
                for (int k = 0; k < 16; k++) myrow[k] = ep[k];
#pragma unroll
                for (int q = 0; q < 7; q++) {
                    float a, b;
                    unpack2(o16p[q], a, b);
                    myrow[16 + 2 * q] = a;
                    myrow[17 + 2 * q] = b;
                }
                float g14, dlg;
                unpack2(o16p[7], g14, dlg);
                myrow[30] = g14;
                density = __expf(fminf(fmaxf(dlg, -15.0f), 15.0f));
            }

            // ---- Layer c1 (31 -> 64) ----
#pragma unroll
            for (int q = 0; q < 32; q++) acc[q] = 0ull;
            for (int i = 0; i < 31; i++) {
                float s = myrow[i];
                unsigned long long ff = pack2(s, s);
                const ulonglong2* wr = reinterpret_cast<const ulonglong2*>(&Wc1s[i << 6]);
#pragma unroll
                for (int q = 0; q < 16; q++) {
                    ulonglong2 wv = wr[q];
                    ffma2(acc[2 * q],     ff, wv.x);
                    ffma2(acc[2 * q + 1], ff, wv.y);
                }
            }
#pragma unroll
            for (int q = 0; q < 32; q++) {
                float a, b;
                unpack2(acc[q], a, b);
                myrow[2 * q]     = fmaxf(a, 0.0f);
                myrow[2 * q + 1] = fmaxf(b, 0.0f);
            }

            // ---- Layer c2 (64 -> 64) ----
#pragma unroll
            for (int q = 0; q < 32; q++) acc[q] = 0ull;
            for (int j = 0; j < 64; j++) {
                float s = myrow[j];
                unsigned long long ff = pack2(s, s);
                const ulonglong2* wr = reinterpret_cast<const ulonglong2*>(&Wc2s[j << 6]);
#pragma unroll
                for (int q = 0; q < 16; q++) {
                    ulonglong2 wv = wr[q];
                    ffma2(acc[2 * q],     ff, wv.x);
                    ffma2(acc[2 * q + 1], ff, wv.y);
                }
            }

            // ---- relu + Layer c3 (64 -> 3) ----
            float r0 = 0.f, r1 = 0.f, r2 = 0.f;
#pragma unroll
            for (int q = 0; q < 32; q++) {
                float a, b;
                unpack2(acc[q], a, b);
                a = fmaxf(a, 0.0f);
                b = fmaxf(b, 0.0f);
                const float* w3a = &Wc3s[(2 * q) * 3];
                r0 += a * w3a[0] + b * w3a[3];
                r1 += a * w3a[1] + b * w3a[4];
                r2 += a * w3a[2] + b * w3a[5];
            }

            float4 res;
            res.x = 1.0f / (1.0f + __expf(-r0));
            res.y = 1.0f / (1.0f + __expf(-r1));
            res.z = 1.0f / (1.0f + __expf(-r2));
            res.w = density;
            *(float4*)&out[p * 4] = res;
        }
        __syncthreads();
    }
}

// ---------------------------------------------------------------------------
// Launch
// ---------------------------------------------------------------------------
extern "C" void kernel_launch(void* const* d_in, const int* in_sizes, int n_in,
                              void* d_out, int out_size)
{
    const float* pts  = (const float*)d_in[0];
    const float* dirs = (const float*)d_in[1];
    const float* ts   = (const float*)d_in[2];
    const float* yl[6];
    const float* yh[6];
    for (int i = 0; i < 6; i++) {
        yl[i] = (const float*)d_in[3 + 2 * i];
        yh[i] = (const float*)d_in[4 + 2 * i];
    }
    const float* W1  = (const float*)d_in[15];
    const float* W2  = (const float*)d_in[16];
    const float* Wc1 = (const float*)d_in[17];
    const float* Wc2 = (const float*)d_in[18];
    const float* Wc3 = (const float*)d_in[19];
    float* out = (float*)d_out;

    static const int hdim[6] = {64, 64, 64, 64, 64, 64};
    static const int wdim[6] = {64, 64, 50, 64, 50, 50};
    static const int offs[6] = {0, 524288, 1048576, 1458176, 1982464, 2392064};

    for (int i = 0; i < 6; i++) {
        int n = 32 * hdim[i] * wdim[i];
        idwt_kernel<<<(n + 511) / 512, 512>>>(yl[i], yh[i], offs[i], hdim[i], wdim[i]);
    }
    enc_kernel<<<(NRAYS + 255) / 256, 256>>>(dirs);

    cudaFuncSetAttribute(wf_main, cudaFuncAttributeMaxDynamicSharedMemorySize, SMEM_BYTES);
    wf_main<<<304, TPB, SMEM_BYTES>>>(pts, ts, W1, W2, Wc1, Wc2, Wc3, out);
}

// round 7
// speedup vs baseline: 1.2042x; 1.2042x over previous
#include <cuda_runtime.h>
#include <math.h>

// ---------------------------------------------------------------------------
// Problem constants: R=8192 rays, S=64 samples, C=32 channels,
// 6 planes coarse dims {64x64,64x64,64x50,64x64,64x50,64x50};
// fine H=128 all, W in {128,128,100,128,100,100}.
// ---------------------------------------------------------------------------
#define NRAYS   8192
#define NSAMP   64
#define NPTS    (NRAYS * NSAMP)     // 524288
#define TPB     256
#define NTILES  (NPTS / TPB)        // 2048

#define PL_TOTAL 2801664            // sum of fine H*W*32 over 6 planes

// Interleaved planes: .x = hi (full idwt), .y = lo (idwt with yh=0)
__device__ float2 g_pl[PL_TOTAL];
__device__ float  g_enc[NRAYS * 16];

// ---------------------------------------------------------------------------
// f32x2 packed-math helpers (FFMA2 only reachable via PTX fma.rn.f32x2)
// ---------------------------------------------------------------------------
__device__ __forceinline__ unsigned long long pack2(float a, float b) {
    unsigned long long r;
    asm("mov.b64 %0, {%1, %2};" : "=l"(r) : "f"(a), "f"(b));
    return r;
}
__device__ __forceinline__ void unpack2(unsigned long long v, float& a, float& b) {
    asm("mov.b64 {%0, %1}, %2;" : "=f"(a), "=f"(b) : "l"(v));
}
__device__ __forceinline__ void ffma2(unsigned long long& acc,
                                      unsigned long long a, unsigned long long b) {
    asm("fma.rn.f32x2 %0, %1, %2, %0;" : "+l"(acc) : "l"(a), "l"(b));
}

// ---------------------------------------------------------------------------
// Kernel 1: inverse Haar DWT -> interleaved float2 {hi, lo}, channel-last.
// fine[2i][2j]=ee, [2i][2j+1]=eo, [2i+1][2j]=oe, [2i+1][2j+1]=oo ; lo = 0.5*a.
// ---------------------------------------------------------------------------
__global__ void idwt_kernel(const float* __restrict__ yl,
                            const float* __restrict__ yh,
                            int outOff, int h, int w)
{
    int id = blockIdx.x * blockDim.x + threadIdx.x;
    int total = h * w * 32;
    if (id >= total) return;
    int c = id & 31;
    int rest = id >> 5;
    int j = rest % w;
    int i = rest / w;
    int hw = h * w;

    float a  = yl[c * hw + i * w + j];
    const float* yhb = yh + (size_t)c * 3 * hw + i * w + j;
    float lh = yhb[0];
    float hl = yhb[hw];
    float hh = yhb[2 * hw];

    int W2 = 2 * w;
    int o = outOff + ((2 * i) * W2 + 2 * j) * 32 + c;

    float ee = 0.5f * (a + lh + hl + hh);
    float eo = 0.5f * (a + lh - hl - hh);
    float oe = 0.5f * (a - lh + hl - hh);
    float oo = 0.5f * (a - lh - hl + hh);
    float l  = 0.5f * a;

    g_pl[o]                = make_float2(ee, l);
    g_pl[o + 32]           = make_float2(eo, l);
    g_pl[o + W2 * 32]      = make_float2(oe, l);
    g_pl[o + W2 * 32 + 32] = make_float2(oo, l);
}

// ---------------------------------------------------------------------------
// Kernel 2: per-ray SH16 direction encoding
// ---------------------------------------------------------------------------
__global__ void enc_kernel(const float* __restrict__ dirs)
{
    int r = blockIdx.x * blockDim.x + threadIdx.x;
    if (r >= NRAYS) return;
    float x = dirs[3 * r + 0];
    float y = dirs[3 * r + 1];
    float z = dirs[3 * r + 2];
    float inv = 1.0f / sqrtf(x * x + y * y + z * z);
    x *= inv; y *= inv; z *= inv;
    float xx = x * x, yy = y * y, zz = z * z;

    float e[16];
    e[0]  = 0.28209479177387814f;
    e[1]  = -0.4886025119029199f * y;
    e[2]  = 0.4886025119029199f * z;
    e[3]  = -0.4886025119029199f * x;
    e[4]  = 1.0925484305920792f * x * y;
    e[5]  = -1.0925484305920792f * y * z;
    e[6]  = 0.31539156525252005f * (3.0f * zz - 1.0f);
    e[7]  = -1.0925484305920792f * x * z;
    e[8]  = 0.5462742152960396f * (xx - yy);
    e[9]  = -0.5900435899266435f * y * (3.0f * xx - yy);
    e[10] = 2.890611442640554f * x * y * z;
    e[11] = -0.4570457994644658f * y * (5.0f * zz - 1.0f);
    e[12] = 0.3731763325901154f * z * (5.0f * zz - 3.0f);
    e[13] = -0.4570457994644658f * x * (5.0f * zz - 1.0f);
    e[14] = 1.445305721320277f * z * (xx - yy);
    e[15] = -0.5900435899266435f * x * (xx - 3.0f * yy);

#pragma unroll
    for (int k = 0; k < 16; k++) g_enc[r * 16 + k] = e[k];
}

// ---------------------------------------------------------------------------
// Kernel 3: fused main kernel. 256 threads, tile = 256 points, 2 CTAs/SM.
// Phase 1: warp-per-point bilerp gathers, lane=channel, LDG.64 float2{hi,lo}.
// Phase 2: thread-per-point MLP chain, packed f32x2 math, smem weights.
// smem (floats):
//   W1s[0,4096) W2s[4096,5120) Wc1s[5120,7104) Wc2s[7104,11200) Wc3s[11200,11392)
//   fs [11392,28032): 256 x 65 rows (stride-65: conflict-free)
// Total 112128 B.
// ---------------------------------------------------------------------------
#define SMEM_FLOATS 28032
#define SMEM_BYTES  (SMEM_FLOATS * 4)

__global__ void __launch_bounds__(TPB, 2) wf_main(
    const float* __restrict__ pts,
    const float* __restrict__ ts,
    const float* __restrict__ W1,
    const float* __restrict__ W2,
    const float* __restrict__ Wc1,
    const float* __restrict__ Wc2,
    const float* __restrict__ Wc3,
    float* __restrict__ out)
{
    extern __shared__ float sm[];
    float* W1s  = sm;
    float* W2s  = sm + 4096;
    float* Wc1s = sm + 5120;
    float* Wc2s = sm + 7104;
    float* Wc3s = sm + 11200;
    float* fs   = sm + 11392;

    int tid = threadIdx.x;
    for (int i = tid; i < 4096; i += TPB) W1s[i]  = W1[i];
    for (int i = tid; i < 1024; i += TPB) W2s[i]  = W2[i];
    for (int i = tid; i < 1984; i += TPB) Wc1s[i] = Wc1[i];
    for (int i = tid; i < 4096; i += TPB) Wc2s[i] = Wc2[i];
    for (int i = tid; i < 192;  i += TPB) Wc3s[i] = Wc3[i];
    __syncthreads();

    const int lane = tid & 31;
    const int wrp  = tid >> 5;

    for (int tile = blockIdx.x; tile < NTILES; tile += gridDim.x) {
        int base = tile * TPB;

        // ---------------- Phase 1: interpolation ----------------
        {
            int myp = base + wrp * 32 + lane;
            float c0r = pts[3 * myp + 0];
            float c1r = pts[3 * myp + 1];
            float c2r = pts[3 * myp + 2];
            float c3r = ts[myp >> 6] * 2.0f - 1.0f;

            for (int it = 0; it < 32; it++) {
                float cc[4];
                cc[0] = __shfl_sync(0xffffffffu, c0r, it);
                cc[1] = __shfl_sync(0xffffffffu, c1r, it);
                cc[2] = __shfl_sync(0xffffffffu, c2r, it);
                cc[3] = __shfl_sync(0xffffffffu, c3r, it);

                float fh = 1.0f, fl = 1.0f;

                const int WplA[6] = {128, 128, 100, 128, 100, 100};
                const int OFFA[6] = {0, 524288, 1048576, 1458176, 1982464, 2392064};
                const int JA[6]   = {0, 0, 0, 1, 1, 2};
                const int KA[6]   = {1, 2, 3, 2, 3, 3};

#pragma unroll
                for (int pl = 0; pl < 6; pl++) {
                    const int Wp = WplA[pl];
                    float yv = (cc[JA[pl]] + 1.0f) * 0.5f * 127.0f;
                    float xv = (cc[KA[pl]] + 1.0f) * 0.5f * (float)(Wp - 1);
                    float y0f = fminf(fmaxf(floorf(yv), 0.0f), 127.0f);
                    float x0f = fminf(fmaxf(floorf(xv), 0.0f), (float)(Wp - 1));
                    float wy = fminf(fmaxf(yv - y0f, 0.0f), 1.0f);
                    float wx = fminf(fmaxf(xv - x0f, 0.0f), 1.0f);
                    int y0 = (int)y0f;
                    int x0 = (int)x0f;
                    int y1 = min(y0 + 1, 127);
                    int x1 = min(x0 + 1, Wp - 1);
                    float w00 = (1.0f - wy) * (1.0f - wx);
                    float w01 = (1.0f - wy) * wx;
                    float w10 = wy * (1.0f - wx);
                    float w11 = wy * wx;

                    int b00 = OFFA[pl] + (y0 * Wp + x0) * 32 + lane;
                    int b01 = OFFA[pl] + (y0 * Wp + x1) * 32 + lane;
                    int b10 = OFFA[pl] + (y1 * Wp + x0) * 32 + lane;
                    int b11 = OFFA[pl] + (y1 * Wp + x1) * 32 + lane;

                    float2 v00 = g_pl[b00];
                    float2 v01 = g_pl[b01];
                    float2 v10 = g_pl[b10];
                    float2 v11 = g_pl[b11];

                    float hv = w00 * v00.x + w01 * v01.x + w10 * v10.x + w11 * v11.x;
                    float lv = w00 * v00.y + w01 * v01.y + w10 * v10.y + w11 * v11.y;
                    fh *= hv;
                    fl *= lv;
                }

                int row = wrp * 32 + it;
                fs[row * 65 + lane]      = fh;
                fs[row * 65 + 32 + lane] = fl;
            }
        }
        __syncthreads();

        // ---------------- Phase 2: packed-f32x2 MLP chain ----------------
        {
            int p = base + tid;
            float* myrow = &fs[tid * 65];

            unsigned long long acc[32];

            // ---- Layer sig1 (64 -> 64): acc[q] = {out[2q], out[2q+1]} ----
#pragma unroll
            for (int q = 0; q < 32; q++) acc[q] = 0ull;
            for (int i = 0; i < 64; i++) {
                float s = myrow[i];
                unsigned long long ff = pack2(s, s);
                const ulonglong2* wr = reinterpret_cast<const ulonglong2*>(&W1s[i << 6]);
#pragma unroll
                for (int q = 0; q < 16; q++) {
                    ulonglong2 wv = wr[q];
                    ffma2(acc[2 * q],     ff, wv.x);
                    ffma2(acc[2 * q + 1], ff, wv.y);
                }
            }
#pragma unroll
            for (int q = 0; q < 32; q++) {
                float a, b;
                unpack2(acc[q], a, b);
                myrow[2 * q]     = fmaxf(a, 0.0f);
                myrow[2 * q + 1] = fmaxf(b, 0.0f);
            }

            // ---- Layer sig2 (64 -> 16) ----
            unsigned long long o16p[8];
#pragma unroll
            for (int k = 0; k < 8; k++) o16p[k] = 0ull;
            for (int j = 0; j < 64; j++) {
                float s = myrow[j];
                unsigned long long ff = pack2(s, s);
                const ulonglong2* wr = reinterpret_cast<const ulonglong2*>(&W2s[j << 4]);
#pragma unroll
                for (int q = 0; q < 4; q++) {
                    ulonglong2 wv = wr[q];
                    ffma2(o16p[2 * q],     ff, wv.x);
                    ffma2(o16p[2 * q + 1], ff, wv.y);
                }
            }

            // density; ci = [enc(16), geo(15)] into smem row
            float density;
            {
                int ray = p >> 6;
                const float* ep = &g_enc[ray * 16];
#pragma unroll
                for (int k = 0; k < 16; k++) myrow[k] = ep[k];
#pragma unroll
                for (int q = 0; q < 7; q++) {
                    float a, b;
                    unpack2(o16p[q], a, b);
                    myrow[16 + 2 * q] = a;
                    myrow[17 + 2 * q] = b;
                }
                float g14, dlg;
                unpack2(o16p[7], g14, dlg);
                myrow[30] = g14;
                density = __expf(fminf(fmaxf(dlg, -15.0f), 15.0f));
            }

            // ---- Layer c1 (31 -> 64) ----
#pragma unroll
            for (int q = 0; q < 32; q++) acc[q] = 0ull;
            for (int i = 0; i < 31; i++) {
                float s = myrow[i];
                unsigned long long ff = pack2(s, s);
                const ulonglong2* wr = reinterpret_cast<const ulonglong2*>(&Wc1s[i << 6]);
#pragma unroll
                for (int q = 0; q < 16; q++) {
                    ulonglong2 wv = wr[q];
                    ffma2(acc[2 * q],     ff, wv.x);
                    ffma2(acc[2 * q + 1], ff, wv.y);
                }
            }
#pragma unroll
            for (int q = 0; q < 32; q++) {
                float a, b;
                unpack2(acc[q], a, b);
                myrow[2 * q]     = fmaxf(a, 0.0f);
                myrow[2 * q + 1] = fmaxf(b, 0.0f);
            }

            // ---- Layer c2 (64 -> 64) ----
#pragma unroll
            for (int q = 0; q < 32; q++) acc[q] = 0ull;
            for (int j = 0; j < 64; j++) {
                float s = myrow[j];
                unsigned long long ff = pack2(s, s);
                const ulonglong2* wr = reinterpret_cast<const ulonglong2*>(&Wc2s[j << 6]);
#pragma unroll
                for (int q = 0; q < 16; q++) {
                    ulonglong2 wv = wr[q];
                    ffma2(acc[2 * q],     ff, wv.x);
                    ffma2(acc[2 * q + 1], ff, wv.y);
                }
            }

            // ---- relu + Layer c3 (64 -> 3) ----
            float r0 = 0.f, r1 = 0.f, r2 = 0.f;
#pragma unroll
            for (int q = 0; q < 32; q++) {
                float a, b;
                unpack2(acc[q], a, b);
                a = fmaxf(a, 0.0f);
                b = fmaxf(b, 0.0f);
                const float* w3a = &Wc3s[(2 * q) * 3];
                r0 += a * w3a[0] + b * w3a[3];
                r1 += a * w3a[1] + b * w3a[4];
                r2 += a * w3a[2] + b * w3a[5];
            }

            float4 res;
            res.x = 1.0f / (1.0f + __expf(-r0));
            res.y = 1.0f / (1.0f + __expf(-r1));
            res.z = 1.0f / (1.0f + __expf(-r2));
            res.w = density;
            *(float4*)&out[p * 4] = res;
        }
        __syncthreads();
    }
}

// ---------------------------------------------------------------------------
// Launch
// ---------------------------------------------------------------------------
extern "C" void kernel_launch(void* const* d_in, const int* in_sizes, int n_in,
                              void* d_out, int out_size)
{
    const float* pts  = (const float*)d_in[0];
    const float* dirs = (const float*)d_in[1];
    const float* ts   = (const float*)d_in[2];
    const float* yl[6];
    const float* yh[6];
    for (int i = 0; i < 6; i++) {
        yl[i] = (const float*)d_in[3 + 2 * i];
        yh[i] = (const float*)d_in[4 + 2 * i];
    }
    const float* W1  = (const float*)d_in[15];
    const float* W2  = (const float*)d_in[16];
    const float* Wc1 = (const float*)d_in[17];
    const float* Wc2 = (const float*)d_in[18];
    const float* Wc3 = (const float*)d_in[19];
    float* out = (float*)d_out;

    static const int hdim[6] = {64, 64, 64, 64, 64, 64};
    static const int wdim[6] = {64, 64, 50, 64, 50, 50};
    static const int offs[6] = {0, 524288, 1048576, 1458176, 1982464, 2392064};

    for (int i = 0; i < 6; i++) {
        int n = 32 * hdim[i] * wdim[i];
        idwt_kernel<<<(n + 511) / 512, 512>>>(yl[i], yh[i], offs[i], hdim[i], wdim[i]);
    }
    enc_kernel<<<(NRAYS + 255) / 256, 256>>>(dirs);

    cudaFuncSetAttribute(wf_main, cudaFuncAttributeMaxDynamicSharedMemorySize, SMEM_BYTES);
    wf_main<<<304, TPB, SMEM_BYTES>>>(pts, ts, W1, W2, Wc1, Wc2, Wc3, out);
}